// round 4
// baseline (speedup 1.0000x reference)
#include <cuda_runtime.h>

// YOLOv3 loss. Full pred arrays are compulsory DRAM traffic at 128B-line
// granularity (po stride 120B touches every line), so stream them coalesced:
// block loads a 256-row tile to smem via float4, extracts the 256 po values,
// softplus only on those. Winner/box/cls corrections handled sparsely.
//
//  pred_large  [64,3,13,13,30]   pred_medium [64,3,26,26,30]
//  pred_small  [64,3,52,52,30]   targets [2048,6]   out[4]={tot,box,obj,cls}

#define NC 25
#define CH 30
#define MAX_CELLS (64*3*(13*13 + 26*26 + 52*52))   // 681408
#define MAXT (3*2048)
#define ROWS_TILE 256
#define TPB 192                   // 1920 float4 per tile / 192 = 10 each

__constant__ float c_anc[9][2] = {
    {116.f,  90.f}, {156.f, 198.f}, {373.f, 326.f},   // grid 13
    { 30.f,  61.f}, { 62.f,  45.f}, { 59.f, 119.f},   // grid 26
    { 10.f,  13.f}, { 16.f,  30.f}, { 33.f,  23.f}};  // grid 52

// 0 = empty (matches static zero-init); main kernel atomicExch's back to 0,
// so state is clean on every graph replay without an init kernel.
__device__ int      g_winner[MAX_CELLS];
__device__ unsigned g_clsmask[MAX_CELLS];
__device__ int      g_list[MAXT];

__device__ __forceinline__ float softplusf(float x) {
    return fmaxf(x, 0.0f) + log1pf(expf(-fabsf(x)));
}
__device__ __forceinline__ float bcef(float x, float t) {
    return softplusf(x) - t * x;
}

__global__ void scatter_kernel(const float* __restrict__ tgt, int N,
                               int off1, int off2, float* __restrict__ out) {
    int idx = blockIdx.x * blockDim.x + threadIdx.x;
    if (idx < 4) out[idx] = 0.0f;
    if (idx >= 3 * N) return;
    int s = idx / N;
    int n = idx - s * N;
    const float* T = tgt + 6 * n;
    int   gridi = (s == 0) ? 13 : (s == 1) ? 26 : 52;
    float gridf = (float)gridi;
    int   off   = (s == 0) ? 0  : (s == 1) ? off1 : off2;

    float txf = T[2] * gridf, tyf = T[3] * gridf;
    float twf = T[4] * gridf, thf = T[5] * gridf;
    int gx = (int)floorf(txf), gy = (int)floorf(tyf);

    int cell = -1;
    if (gx >= 0 && gx < gridi && gy >= 0 && gy < gridi) {
        int bi  = (int)T[0];
        int cid = (int)T[1];
        float best_iou = -1.0f; int best = 0;
        #pragma unroll
        for (int a = 0; a < 3; a++) {
            float saw = c_anc[s*3 + a][0] / gridf;
            float sah = c_anc[s*3 + a][1] / gridf;
            float inter = fminf(twf, saw) * fminf(thf, sah);
            float uni   = twf * thf + saw * sah - inter;
            float iou   = inter / (uni + 1e-9f);
            if (iou > best_iou) { best_iou = iou; best = a; }   // first-max (argmax)
        }
        cell = off + ((bi * 3 + best) * gridi + gy) * gridi + gx;
        atomicMax(&g_winner[cell], n + 1);        // last target index wins
        atomicOr(&g_clsmask[cell], 1u << cid);    // class union on collision
    }
    g_list[idx] = cell;
}

__global__ void __launch_bounds__(TPB)
main_kernel(const float* __restrict__ pl,
            const float* __restrict__ pm,
            const float* __restrict__ ps,
            const float* __restrict__ tgt,
            float* __restrict__ out,
            int off1, int off2,
            int t0, int t1,            // tile counts for arrays 0,1
            int r0, int r1, int r2,    // row (cell) counts per array
            int nT) {
    __shared__ float s[ROWS_TILE * CH];       // 30 KB
    int t = threadIdx.x;
    int b = blockIdx.x;

    // ---- map block -> (array, tile) ----
    const float* p; int rows_total, tile;
    if (b < t0)           { p = pl; rows_total = r0; tile = b; }
    else if (b < t0 + t1) { p = pm; rows_total = r1; tile = b - t0; }
    else                  { p = ps; rows_total = r2; tile = b - t0 - t1; }

    int row0 = tile * ROWS_TILE;
    int rows = rows_total - row0;
    if (rows > ROWS_TILE) rows = ROWS_TILE;
    int nv4 = (rows * CH) >> 2;               // rows*30/4 (rows even)

    const float4* src = (const float4*)(p + (long long)row0 * CH);
    #pragma unroll
    for (int k = 0; k < 10; k++) {
        int i = k * TPB + t;
        if (i < nv4) ((float4*)s)[i] = __ldg(src + i);
    }
    __syncthreads();

    float box = 0.0f, obj = 0.0f, cls = 0.0f;

    // ---- obj base: 0.5*softplus(po) for rows in this tile ----
    for (int c = t; c < rows; c += TPB)
        obj += 0.5f * softplusf(s[c * CH + 4]);

    // ---- winner corrections on first nT global threads ----
    int gid = b * TPB + t;
    if (gid < nT) {
        int cell = g_list[gid];
        if (cell >= 0) {
            int w = atomicExch(&g_winner[cell], 0);       // claim + clean
            if (w > 0) {
                unsigned m = atomicExch(&g_clsmask[cell], 0u);
                int n = w - 1;
                const float* pp; int local; float gridf; int sc;
                if (cell < off1)      { pp = pl; local = cell;        gridf = 13.0f; sc = 0; }
                else if (cell < off2) { pp = pm; local = cell - off1; gridf = 26.0f; sc = 1; }
                else                  { pp = ps; local = cell - off2; gridf = 52.0f; sc = 2; }
                const float* P  = pp + (long long)local * CH;
                const float* Tg = tgt + 6 * n;

                float txf = Tg[2] * gridf, tyf = Tg[3] * gridf;
                float twf = Tg[4] * gridf, thf = Tg[5] * gridf;

                float best_iou = -1.0f, saw_b = 1.0f, sah_b = 1.0f;
                #pragma unroll
                for (int a = 0; a < 3; a++) {
                    float saw = c_anc[sc*3 + a][0] / gridf;
                    float sah = c_anc[sc*3 + a][1] / gridf;
                    float inter = fminf(twf, saw) * fminf(thf, sah);
                    float uni   = twf * thf + saw * sah - inter;
                    float iou   = inter / (uni + 1e-9f);
                    if (iou > best_iou) { best_iou = iou; saw_b = saw; sah_b = sah; }
                }
                float tx = txf - floorf(txf);
                float ty = tyf - floorf(tyf);
                float tw = logf(twf / saw_b + 1e-16f);
                float th = logf(thf / sah_b + 1e-16f);

                float px = P[0], py = P[1], pw = P[2], ph = P[3], po = P[4];
                float dw = pw - tw, dh = ph - th;
                box = 5.0f * (bcef(px, tx) + bcef(py, ty) + dw * dw + dh * dh);

                // winner obj: softplus(-po); base already added 0.5*softplus(po)
                obj += 0.5f * softplusf(po) - po;

                #pragma unroll
                for (int c = 0; c < NC; c++) {
                    float pc = P[5 + c];
                    cls += softplusf(pc) - (((m >> c) & 1u) ? pc : 0.0f);
                }
            }
        }
    }

    // ---- block reduction (6 warps) then 4 atomics per block ----
    #pragma unroll
    for (int o = 16; o > 0; o >>= 1) {
        box += __shfl_down_sync(0xFFFFFFFFu, box, o);
        obj += __shfl_down_sync(0xFFFFFFFFu, obj, o);
        cls += __shfl_down_sync(0xFFFFFFFFu, cls, o);
    }
    __shared__ float sb[6], so[6], sccl[6];
    int lane = t & 31, warp = t >> 5;
    if (lane == 0) { sb[warp] = box; so[warp] = obj; sccl[warp] = cls; }
    __syncthreads();
    if (warp == 0) {
        box = (lane < 6) ? sb[lane] : 0.0f;
        obj = (lane < 6) ? so[lane] : 0.0f;
        cls = (lane < 6) ? sccl[lane] : 0.0f;
        #pragma unroll
        for (int o = 4; o > 0; o >>= 1) {
            box += __shfl_down_sync(0xFFFFFFFFu, box, o);
            obj += __shfl_down_sync(0xFFFFFFFFu, obj, o);
            cls += __shfl_down_sync(0xFFFFFFFFu, cls, o);
        }
        if (lane == 0) {
            atomicAdd(out + 0, box + obj + cls);
            atomicAdd(out + 1, box);
            atomicAdd(out + 2, obj);
            atomicAdd(out + 3, cls);
        }
    }
}

extern "C" void kernel_launch(void* const* d_in, const int* in_sizes, int n_in,
                              void* d_out, int out_size) {
    const float* pl  = (const float*)d_in[0];
    const float* pm  = (const float*)d_in[1];
    const float* ps  = (const float*)d_in[2];
    const float* tgt = (const float*)d_in[3];
    float* out = (float*)d_out;

    int B = in_sizes[0] / (3 * 13 * 13 * CH);
    int N = in_sizes[3] / 6;
    int r0 = B * 3 * 13 * 13;
    int r1 = B * 3 * 26 * 26;
    int r2 = B * 3 * 52 * 52;
    int off1 = r0, off2 = r0 + r1;
    int nT = 3 * N;

    int t0 = (r0 + ROWS_TILE - 1) / ROWS_TILE;
    int t1 = (r1 + ROWS_TILE - 1) / ROWS_TILE;
    int t2 = (r2 + ROWS_TILE - 1) / ROWS_TILE;

    scatter_kernel<<<(nT + 255) / 256, 256>>>(tgt, N, off1, off2, out);
    main_kernel<<<t0 + t1 + t2, TPB>>>(pl, pm, ps, tgt, out,
                                       off1, off2, t0, t1, r0, r1, r2, nT);
}

// round 5
// speedup vs baseline: 1.0575x; 1.0575x over previous
#include <cuda_runtime.h>

// YOLOv3 loss. The po channel (stride 120B) touches every 128B line, so the
// full 82MB pred read is compulsory -> stream it coalesced with float4 loads,
// register-only (no smem, no sync). po appears in a float4 iff (j%15)==1 (x)
// or (j%15)==8 (z). Winner/box/cls corrections handled sparsely by the first
// 6144 threads; device state self-cleans via atomicExch for graph replay.
//
//  pred_large  [64,3,13,13,30]   pred_medium [64,3,26,26,30]
//  pred_small  [64,3,52,52,30]   targets [2048,6]   out[4]={tot,box,obj,cls}

#define NC 25
#define CH 30
#define MAX_CELLS (64*3*(13*13 + 26*26 + 52*52))   // 681408
#define MAXT (3*2048)
#define TPB 256
#define UNROLL 8
#define CHUNK (TPB * UNROLL)      // 2048 float4 per block

__constant__ float c_anc[9][2] = {
    {116.f,  90.f}, {156.f, 198.f}, {373.f, 326.f},   // grid 13
    { 30.f,  61.f}, { 62.f,  45.f}, { 59.f, 119.f},   // grid 26
    { 10.f,  13.f}, { 16.f,  30.f}, { 33.f,  23.f}};  // grid 52

__device__ int      g_winner[MAX_CELLS];   // 0 = empty; self-cleaning
__device__ unsigned g_clsmask[MAX_CELLS];
__device__ int      g_list[MAXT];

__device__ __forceinline__ float softplusf(float x) {
    return fmaxf(x, 0.0f) + log1pf(expf(-fabsf(x)));
}
__device__ __forceinline__ float bcef(float x, float t) {
    return softplusf(x) - t * x;
}

__global__ void scatter_kernel(const float* __restrict__ tgt, int N,
                               int off1, int off2, float* __restrict__ out) {
    int idx = blockIdx.x * blockDim.x + threadIdx.x;
    if (idx < 4) out[idx] = 0.0f;
    if (idx >= 3 * N) return;
    int s = idx / N;
    int n = idx - s * N;
    const float* T = tgt + 6 * n;
    int   gridi = (s == 0) ? 13 : (s == 1) ? 26 : 52;
    float gridf = (float)gridi;
    int   off   = (s == 0) ? 0  : (s == 1) ? off1 : off2;

    float txf = T[2] * gridf, tyf = T[3] * gridf;
    float twf = T[4] * gridf, thf = T[5] * gridf;
    int gx = (int)floorf(txf), gy = (int)floorf(tyf);

    int cell = -1;
    if (gx >= 0 && gx < gridi && gy >= 0 && gy < gridi) {
        int bi  = (int)T[0];
        int cid = (int)T[1];
        float best_iou = -1.0f; int best = 0;
        #pragma unroll
        for (int a = 0; a < 3; a++) {
            float saw = c_anc[s*3 + a][0] / gridf;
            float sah = c_anc[s*3 + a][1] / gridf;
            float inter = fminf(twf, saw) * fminf(thf, sah);
            float uni   = twf * thf + saw * sah - inter;
            float iou   = inter / (uni + 1e-9f);
            if (iou > best_iou) { best_iou = iou; best = a; }   // first-max (argmax)
        }
        cell = off + ((bi * 3 + best) * gridi + gy) * gridi + gx;
        atomicMax(&g_winner[cell], n + 1);        // last target index wins
        atomicOr(&g_clsmask[cell], 1u << cid);    // class union on collision
    }
    g_list[idx] = cell;
}

__global__ void __launch_bounds__(TPB)
main_kernel(const float* __restrict__ pl,
            const float* __restrict__ pm,
            const float* __restrict__ ps,
            const float* __restrict__ tgt,
            float* __restrict__ out,
            int off1, int off2,
            int b0, int b1,              // block counts for arrays 0,1
            int n0, int n1, int n2,      // float4 counts per array
            int nT) {
    int b = blockIdx.x, t = threadIdx.x;

    // ---- map block -> (array, float4 chunk) ----
    const float4* src; int nf4, cb;
    if (b < b0)           { src = (const float4*)pl; nf4 = n0; cb = b * CHUNK; }
    else if (b < b0 + b1) { src = (const float4*)pm; nf4 = n1; cb = (b - b0) * CHUNK; }
    else                  { src = (const float4*)ps; nf4 = n2; cb = (b - b0 - b1) * CHUNK; }

    float box = 0.0f, obj = 0.0f, cls = 0.0f;

    // ---- coalesced stream: 8 independent float4 loads, extract po in regs ----
    {
        float4 v[UNROLL];
        int    j[UNROLL];
        #pragma unroll
        for (int k = 0; k < UNROLL; k++) {
            j[k] = cb + k * TPB + t;
            if (j[k] < nf4) v[k] = src[j[k]];
            else            v[k] = make_float4(-100.f, -100.f, -100.f, -100.f);
        }
        #pragma unroll
        for (int k = 0; k < UNROLL; k++) {
            unsigned jm = (unsigned)j[k] % 15u;      // elem 4j mod 30 == 4 or 2
            float po = (jm == 1u) ? v[k].x : ((jm == 8u) ? v[k].z : -100.0f);
            obj += 0.5f * softplusf(po);             // softplus(-100) == 0
        }
    }

    // ---- winner corrections on first nT global threads (self-cleaning) ----
    int gid = b * TPB + t;
    if (gid < nT) {
        int cell = g_list[gid];
        if (cell >= 0) {
            int w = atomicExch(&g_winner[cell], 0);       // claim + clean
            if (w > 0) {
                unsigned m = atomicExch(&g_clsmask[cell], 0u);
                int n = w - 1;
                const float* pp; int local; float gridf; int sc;
                if (cell < off1)      { pp = pl; local = cell;        gridf = 13.0f; sc = 0; }
                else if (cell < off2) { pp = pm; local = cell - off1; gridf = 26.0f; sc = 1; }
                else                  { pp = ps; local = cell - off2; gridf = 52.0f; sc = 2; }
                const float* P  = pp + (long long)local * CH;
                const float* Tg = tgt + 6 * n;

                float txf = Tg[2] * gridf, tyf = Tg[3] * gridf;
                float twf = Tg[4] * gridf, thf = Tg[5] * gridf;

                float best_iou = -1.0f, saw_b = 1.0f, sah_b = 1.0f;
                #pragma unroll
                for (int a = 0; a < 3; a++) {
                    float saw = c_anc[sc*3 + a][0] / gridf;
                    float sah = c_anc[sc*3 + a][1] / gridf;
                    float inter = fminf(twf, saw) * fminf(thf, sah);
                    float uni   = twf * thf + saw * sah - inter;
                    float iou   = inter / (uni + 1e-9f);
                    if (iou > best_iou) { best_iou = iou; saw_b = saw; sah_b = sah; }
                }
                float tx = txf - floorf(txf);
                float ty = tyf - floorf(tyf);
                float tw = logf(twf / saw_b + 1e-16f);
                float th = logf(thf / sah_b + 1e-16f);

                float px = P[0], py = P[1], pw = P[2], ph = P[3], po = P[4];
                float dw = pw - tw, dh = ph - th;
                box = 5.0f * (bcef(px, tx) + bcef(py, ty) + dw * dw + dh * dh);

                // winner obj: softplus(-po); base already contributed 0.5*softplus(po)
                obj += 0.5f * softplusf(po) - po;

                #pragma unroll
                for (int c = 0; c < NC; c++) {
                    float pc = P[5 + c];
                    cls += softplusf(pc) - (((m >> c) & 1u) ? pc : 0.0f);
                }
            }
        }
    }

    // ---- block reduction then 4 atomics per block ----
    #pragma unroll
    for (int o = 16; o > 0; o >>= 1) {
        box += __shfl_down_sync(0xFFFFFFFFu, box, o);
        obj += __shfl_down_sync(0xFFFFFFFFu, obj, o);
        cls += __shfl_down_sync(0xFFFFFFFFu, cls, o);
    }
    __shared__ float sb[8], so[8], sc2[8];
    int lane = t & 31, warp = t >> 5;
    if (lane == 0) { sb[warp] = box; so[warp] = obj; sc2[warp] = cls; }
    __syncthreads();
    if (warp == 0) {
        box = (lane < 8) ? sb[lane] : 0.0f;
        obj = (lane < 8) ? so[lane] : 0.0f;
        cls = (lane < 8) ? sc2[lane] : 0.0f;
        #pragma unroll
        for (int o = 4; o > 0; o >>= 1) {
            box += __shfl_down_sync(0xFFFFFFFFu, box, o);
            obj += __shfl_down_sync(0xFFFFFFFFu, obj, o);
            cls += __shfl_down_sync(0xFFFFFFFFu, cls, o);
        }
        if (lane == 0) {
            atomicAdd(out + 0, box + obj + cls);
            atomicAdd(out + 1, box);
            atomicAdd(out + 2, obj);
            atomicAdd(out + 3, cls);
        }
    }
}

extern "C" void kernel_launch(void* const* d_in, const int* in_sizes, int n_in,
                              void* d_out, int out_size) {
    const float* pl  = (const float*)d_in[0];
    const float* pm  = (const float*)d_in[1];
    const float* ps  = (const float*)d_in[2];
    const float* tgt = (const float*)d_in[3];
    float* out = (float*)d_out;

    int B = in_sizes[0] / (3 * 13 * 13 * CH);
    int N = in_sizes[3] / 6;
    int r0 = B * 3 * 13 * 13;
    int r1 = B * 3 * 26 * 26;
    int r2 = B * 3 * 52 * 52;
    int off1 = r0, off2 = r0 + r1;
    int nT = 3 * N;

    int n0 = r0 * CH / 4;          // float4 counts (all divisible by 4)
    int n1 = r1 * CH / 4;
    int n2 = r2 * CH / 4;
    int b0 = (n0 + CHUNK - 1) / CHUNK;
    int b1 = (n1 + CHUNK - 1) / CHUNK;
    int b2 = (n2 + CHUNK - 1) / CHUNK;

    scatter_kernel<<<(nT + 255) / 256, 256>>>(tgt, N, off1, off2, out);
    main_kernel<<<b0 + b1 + b2, TPB>>>(pl, pm, ps, tgt, out,
                                       off1, off2, b0, b1, n0, n1, n2, nT);
}

// round 6
// speedup vs baseline: 1.5477x; 1.4636x over previous
#include <cuda_runtime.h>

// YOLOv3 loss. Only the po channel (elem 30r+4) is needed densely; DRAM pulls
// full lines anyway, so minimize SM-side work: po-only scalar streaming loads
// at high occupancy. Row pair m -> po at flat indices 60m+4 and 60m+34.
// Winner/box/cls corrections handled sparsely; device state self-cleans via
// atomicExch so the kernel is graph-replay safe with no init pass.
//
//  pred_large  [64,3,13,13,30]   pred_medium [64,3,26,26,30]
//  pred_small  [64,3,52,52,30]   targets [2048,6]   out[4]={tot,box,obj,cls}

#define NC 25
#define CH 30
#define MAX_CELLS (64*3*(13*13 + 26*26 + 52*52))   // 681408
#define MAXT (3*2048)
#define TPB 256
#define UPT 2
#define MCHUNK (TPB * UPT)        // 512 row-pairs per block

__constant__ float c_anc[9][2] = {
    {116.f,  90.f}, {156.f, 198.f}, {373.f, 326.f},   // grid 13
    { 30.f,  61.f}, { 62.f,  45.f}, { 59.f, 119.f},   // grid 26
    { 10.f,  13.f}, { 16.f,  30.f}, { 33.f,  23.f}};  // grid 52

__device__ int      g_winner[MAX_CELLS];   // 0 = empty; self-cleaning
__device__ unsigned g_clsmask[MAX_CELLS];
__device__ int      g_list[MAXT];

__device__ __forceinline__ float softplusf(float x) {
    return fmaxf(x, 0.0f) + log1pf(expf(-fabsf(x)));
}
__device__ __forceinline__ float bcef(float x, float t) {
    return softplusf(x) - t * x;
}

__global__ void scatter_kernel(const float* __restrict__ tgt, int N,
                               int off1, int off2, float* __restrict__ out) {
    int idx = blockIdx.x * blockDim.x + threadIdx.x;
    if (idx < 4) out[idx] = 0.0f;
    if (idx >= 3 * N) return;
    int s = idx / N;
    int n = idx - s * N;
    const float* T = tgt + 6 * n;
    int   gridi = (s == 0) ? 13 : (s == 1) ? 26 : 52;
    float gridf = (float)gridi;
    int   off   = (s == 0) ? 0  : (s == 1) ? off1 : off2;

    float txf = T[2] * gridf, tyf = T[3] * gridf;
    float twf = T[4] * gridf, thf = T[5] * gridf;
    int gx = (int)floorf(txf), gy = (int)floorf(tyf);

    int cell = -1;
    if (gx >= 0 && gx < gridi && gy >= 0 && gy < gridi) {
        int bi  = (int)T[0];
        int cid = (int)T[1];
        float best_iou = -1.0f; int best = 0;
        #pragma unroll
        for (int a = 0; a < 3; a++) {
            float saw = c_anc[s*3 + a][0] / gridf;
            float sah = c_anc[s*3 + a][1] / gridf;
            float inter = fminf(twf, saw) * fminf(thf, sah);
            float uni   = twf * thf + saw * sah - inter;
            float iou   = inter / (uni + 1e-9f);
            if (iou > best_iou) { best_iou = iou; best = a; }   // first-max (argmax)
        }
        cell = off + ((bi * 3 + best) * gridi + gy) * gridi + gx;
        atomicMax(&g_winner[cell], n + 1);        // last target index wins
        atomicOr(&g_clsmask[cell], 1u << cid);    // class union on collision
    }
    g_list[idx] = cell;
}

__global__ void __launch_bounds__(TPB)
main_kernel(const float* __restrict__ pl,
            const float* __restrict__ pm,
            const float* __restrict__ ps,
            const float* __restrict__ tgt,
            float* __restrict__ out,
            int off1, int off2,
            int blk0, int blk1,          // block counts for arrays 0,1
            int m0, int m1, int m2,      // row-pair counts per array
            int nT) {
    int b = blockIdx.x, t = threadIdx.x;

    // ---- map block -> (array, row-pair chunk) ----
    const float* p; int mcnt, mb;
    if (b < blk0)             { p = pl; mcnt = m0; mb = b * MCHUNK; }
    else if (b < blk0 + blk1) { p = pm; mcnt = m1; mb = (b - blk0) * MCHUNK; }
    else                      { p = ps; mcnt = m2; mb = (b - blk0 - blk1) * MCHUNK; }

    float box = 0.0f, obj = 0.0f, cls = 0.0f;

    // ---- po-only stream: 4 independent scalar loads per thread ----
    {
        float v[2 * UPT];
        #pragma unroll
        for (int k = 0; k < UPT; k++) {
            int m = mb + k * TPB + t;
            if (m < mcnt) {
                long long base = 60LL * m;
                v[2*k]   = __ldcs(p + base + 4);    // po of row 2m
                v[2*k+1] = __ldcs(p + base + 34);   // po of row 2m+1
            } else {
                v[2*k] = v[2*k+1] = -100.0f;        // softplus(-100) == 0
            }
        }
        #pragma unroll
        for (int k = 0; k < 2 * UPT; k++) obj += 0.5f * softplusf(v[k]);
    }

    // ---- winner corrections on first nT global threads (self-cleaning) ----
    int gid = b * TPB + t;
    if (gid < nT) {
        int cell = g_list[gid];
        if (cell >= 0) {
            int w = atomicExch(&g_winner[cell], 0);       // claim + clean
            if (w > 0) {
                unsigned m = atomicExch(&g_clsmask[cell], 0u);
                int n = w - 1;
                const float* pp; int local; float gridf; int sc;
                if (cell < off1)      { pp = pl; local = cell;        gridf = 13.0f; sc = 0; }
                else if (cell < off2) { pp = pm; local = cell - off1; gridf = 26.0f; sc = 1; }
                else                  { pp = ps; local = cell - off2; gridf = 52.0f; sc = 2; }
                const float* P  = pp + (long long)local * CH;
                const float* Tg = tgt + 6 * n;

                float txf = Tg[2] * gridf, tyf = Tg[3] * gridf;
                float twf = Tg[4] * gridf, thf = Tg[5] * gridf;

                float best_iou = -1.0f, saw_b = 1.0f, sah_b = 1.0f;
                #pragma unroll
                for (int a = 0; a < 3; a++) {
                    float saw = c_anc[sc*3 + a][0] / gridf;
                    float sah = c_anc[sc*3 + a][1] / gridf;
                    float inter = fminf(twf, saw) * fminf(thf, sah);
                    float uni   = twf * thf + saw * sah - inter;
                    float iou   = inter / (uni + 1e-9f);
                    if (iou > best_iou) { best_iou = iou; saw_b = saw; sah_b = sah; }
                }
                float tx = txf - floorf(txf);
                float ty = tyf - floorf(tyf);
                float tw = logf(twf / saw_b + 1e-16f);
                float th = logf(thf / sah_b + 1e-16f);

                float px = P[0], py = P[1], pw = P[2], ph = P[3], po = P[4];
                float dw = pw - tw, dh = ph - th;
                box = 5.0f * (bcef(px, tx) + bcef(py, ty) + dw * dw + dh * dh);

                // winner obj: softplus(-po); base already contributed 0.5*softplus(po)
                obj += 0.5f * softplusf(po) - po;

                #pragma unroll
                for (int c = 0; c < NC; c++) {
                    float pc = P[5 + c];
                    cls += softplusf(pc) - (((m >> c) & 1u) ? pc : 0.0f);
                }
            }
        }
    }

    // ---- block reduction then 4 atomics per block ----
    #pragma unroll
    for (int o = 16; o > 0; o >>= 1) {
        box += __shfl_down_sync(0xFFFFFFFFu, box, o);
        obj += __shfl_down_sync(0xFFFFFFFFu, obj, o);
        cls += __shfl_down_sync(0xFFFFFFFFu, cls, o);
    }
    __shared__ float sb[8], so[8], sc2[8];
    int lane = t & 31, warp = t >> 5;
    if (lane == 0) { sb[warp] = box; so[warp] = obj; sc2[warp] = cls; }
    __syncthreads();
    if (warp == 0) {
        box = (lane < 8) ? sb[lane] : 0.0f;
        obj = (lane < 8) ? so[lane] : 0.0f;
        cls = (lane < 8) ? sc2[lane] : 0.0f;
        #pragma unroll
        for (int o = 4; o > 0; o >>= 1) {
            box += __shfl_down_sync(0xFFFFFFFFu, box, o);
            obj += __shfl_down_sync(0xFFFFFFFFu, obj, o);
            cls += __shfl_down_sync(0xFFFFFFFFu, cls, o);
        }
        if (lane == 0) {
            atomicAdd(out + 0, box + obj + cls);
            atomicAdd(out + 1, box);
            atomicAdd(out + 2, obj);
            atomicAdd(out + 3, cls);
        }
    }
}

extern "C" void kernel_launch(void* const* d_in, const int* in_sizes, int n_in,
                              void* d_out, int out_size) {
    const float* pl  = (const float*)d_in[0];
    const float* pm  = (const float*)d_in[1];
    const float* ps  = (const float*)d_in[2];
    const float* tgt = (const float*)d_in[3];
    float* out = (float*)d_out;

    int B = in_sizes[0] / (3 * 13 * 13 * CH);
    int N = in_sizes[3] / 6;
    int r0 = B * 3 * 13 * 13;
    int r1 = B * 3 * 26 * 26;
    int r2 = B * 3 * 52 * 52;
    int off1 = r0, off2 = r0 + r1;
    int nT = 3 * N;

    int m0 = r0 / 2, m1 = r1 / 2, m2 = r2 / 2;   // row-pair counts (rows even)
    int blk0 = (m0 + MCHUNK - 1) / MCHUNK;
    int blk1 = (m1 + MCHUNK - 1) / MCHUNK;
    int blk2 = (m2 + MCHUNK - 1) / MCHUNK;

    scatter_kernel<<<(nT + 255) / 256, 256>>>(tgt, N, off1, off2, out);
    main_kernel<<<blk0 + blk1 + blk2, TPB>>>(pl, pm, ps, tgt, out,
                                             off1, off2, blk0, blk1,
                                             m0, m1, m2, nT);
}

// round 7
// speedup vs baseline: 1.5506x; 1.0019x over previous
#include <cuda_runtime.h>

// YOLOv3 loss. Only the po channel (elem 30r+4) is needed densely; DRAM pulls
// full lines anyway, so minimize SM-side work: po-only scalar streaming loads
// at high occupancy. Row pair m -> po at flat indices 60m+4 and 60m+34.
// Winner/box/cls corrections handled sparsely; device state self-cleans via
// atomicExch so the kernel is graph-replay safe with no init pass.
//
//  pred_large  [64,3,13,13,30]   pred_medium [64,3,26,26,30]
//  pred_small  [64,3,52,52,30]   targets [2048,6]   out[4]={tot,box,obj,cls}

#define NC 25
#define CH 30
#define MAX_CELLS (64*3*(13*13 + 26*26 + 52*52))   // 681408
#define MAXT (3*2048)
#define TPB 256
#define UPT 2
#define MCHUNK (TPB * UPT)        // 512 row-pairs per block

__constant__ float c_anc[9][2] = {
    {116.f,  90.f}, {156.f, 198.f}, {373.f, 326.f},   // grid 13
    { 30.f,  61.f}, { 62.f,  45.f}, { 59.f, 119.f},   // grid 26
    { 10.f,  13.f}, { 16.f,  30.f}, { 33.f,  23.f}};  // grid 52

__device__ int      g_winner[MAX_CELLS];   // 0 = empty; self-cleaning
__device__ unsigned g_clsmask[MAX_CELLS];
__device__ int      g_list[MAXT];

__device__ __forceinline__ float softplusf(float x) {
    return fmaxf(x, 0.0f) + log1pf(expf(-fabsf(x)));
}
__device__ __forceinline__ float bcef(float x, float t) {
    return softplusf(x) - t * x;
}

__global__ void scatter_kernel(const float* __restrict__ tgt, int N,
                               int off1, int off2, float* __restrict__ out) {
    int idx = blockIdx.x * blockDim.x + threadIdx.x;
    if (idx < 4) out[idx] = 0.0f;
    if (idx >= 3 * N) return;
    int s = idx / N;
    int n = idx - s * N;
    const float* T = tgt + 6 * n;
    int   gridi = (s == 0) ? 13 : (s == 1) ? 26 : 52;
    float gridf = (float)gridi;
    int   off   = (s == 0) ? 0  : (s == 1) ? off1 : off2;

    float txf = T[2] * gridf, tyf = T[3] * gridf;
    float twf = T[4] * gridf, thf = T[5] * gridf;
    int gx = (int)floorf(txf), gy = (int)floorf(tyf);

    int cell = -1;
    if (gx >= 0 && gx < gridi && gy >= 0 && gy < gridi) {
        int bi  = (int)T[0];
        int cid = (int)T[1];
        float best_iou = -1.0f; int best = 0;
        #pragma unroll
        for (int a = 0; a < 3; a++) {
            float saw = c_anc[s*3 + a][0] / gridf;
            float sah = c_anc[s*3 + a][1] / gridf;
            float inter = fminf(twf, saw) * fminf(thf, sah);
            float uni   = twf * thf + saw * sah - inter;
            float iou   = inter / (uni + 1e-9f);
            if (iou > best_iou) { best_iou = iou; best = a; }   // first-max (argmax)
        }
        cell = off + ((bi * 3 + best) * gridi + gy) * gridi + gx;
        atomicMax(&g_winner[cell], n + 1);        // last target index wins
        atomicOr(&g_clsmask[cell], 1u << cid);    // class union on collision
    }
    g_list[idx] = cell;
}

__global__ void __launch_bounds__(TPB)
main_kernel(const float* __restrict__ pl,
            const float* __restrict__ pm,
            const float* __restrict__ ps,
            const float* __restrict__ tgt,
            float* __restrict__ out,
            int off1, int off2,
            int blk0, int blk1,          // block counts for arrays 0,1
            int m0, int m1, int m2,      // row-pair counts per array
            int nT) {
    int b = blockIdx.x, t = threadIdx.x;

    // ---- map block -> (array, row-pair chunk) ----
    const float* p; int mcnt, mb;
    if (b < blk0)             { p = pl; mcnt = m0; mb = b * MCHUNK; }
    else if (b < blk0 + blk1) { p = pm; mcnt = m1; mb = (b - blk0) * MCHUNK; }
    else                      { p = ps; mcnt = m2; mb = (b - blk0 - blk1) * MCHUNK; }

    float box = 0.0f, obj = 0.0f, cls = 0.0f;

    // ---- po-only stream: 4 independent scalar loads per thread ----
    {
        float v[2 * UPT];
        #pragma unroll
        for (int k = 0; k < UPT; k++) {
            int m = mb + k * TPB + t;
            if (m < mcnt) {
                long long base = 60LL * m;
                v[2*k]   = __ldcs(p + base + 4);    // po of row 2m
                v[2*k+1] = __ldcs(p + base + 34);   // po of row 2m+1
            } else {
                v[2*k] = v[2*k+1] = -100.0f;        // softplus(-100) == 0
            }
        }
        #pragma unroll
        for (int k = 0; k < 2 * UPT; k++) obj += 0.5f * softplusf(v[k]);
    }

    // ---- winner corrections on first nT global threads (self-cleaning) ----
    int gid = b * TPB + t;
    if (gid < nT) {
        int cell = g_list[gid];
        if (cell >= 0) {
            int w = atomicExch(&g_winner[cell], 0);       // claim + clean
            if (w > 0) {
                unsigned m = atomicExch(&g_clsmask[cell], 0u);
                int n = w - 1;
                const float* pp; int local; float gridf; int sc;
                if (cell < off1)      { pp = pl; local = cell;        gridf = 13.0f; sc = 0; }
                else if (cell < off2) { pp = pm; local = cell - off1; gridf = 26.0f; sc = 1; }
                else                  { pp = ps; local = cell - off2; gridf = 52.0f; sc = 2; }
                const float* P  = pp + (long long)local * CH;
                const float* Tg = tgt + 6 * n;

                float txf = Tg[2] * gridf, tyf = Tg[3] * gridf;
                float twf = Tg[4] * gridf, thf = Tg[5] * gridf;

                float best_iou = -1.0f, saw_b = 1.0f, sah_b = 1.0f;
                #pragma unroll
                for (int a = 0; a < 3; a++) {
                    float saw = c_anc[sc*3 + a][0] / gridf;
                    float sah = c_anc[sc*3 + a][1] / gridf;
                    float inter = fminf(twf, saw) * fminf(thf, sah);
                    float uni   = twf * thf + saw * sah - inter;
                    float iou   = inter / (uni + 1e-9f);
                    if (iou > best_iou) { best_iou = iou; saw_b = saw; sah_b = sah; }
                }
                float tx = txf - floorf(txf);
                float ty = tyf - floorf(tyf);
                float tw = logf(twf / saw_b + 1e-16f);
                float th = logf(thf / sah_b + 1e-16f);

                float px = P[0], py = P[1], pw = P[2], ph = P[3], po = P[4];
                float dw = pw - tw, dh = ph - th;
                box = 5.0f * (bcef(px, tx) + bcef(py, ty) + dw * dw + dh * dh);

                // winner obj: softplus(-po); base already contributed 0.5*softplus(po)
                obj += 0.5f * softplusf(po) - po;

                #pragma unroll
                for (int c = 0; c < NC; c++) {
                    float pc = P[5 + c];
                    cls += softplusf(pc) - (((m >> c) & 1u) ? pc : 0.0f);
                }
            }
        }
    }

    // ---- block reduction then 4 atomics per block ----
    #pragma unroll
    for (int o = 16; o > 0; o >>= 1) {
        box += __shfl_down_sync(0xFFFFFFFFu, box, o);
        obj += __shfl_down_sync(0xFFFFFFFFu, obj, o);
        cls += __shfl_down_sync(0xFFFFFFFFu, cls, o);
    }
    __shared__ float sb[8], so[8], sc2[8];
    int lane = t & 31, warp = t >> 5;
    if (lane == 0) { sb[warp] = box; so[warp] = obj; sc2[warp] = cls; }
    __syncthreads();
    if (warp == 0) {
        box = (lane < 8) ? sb[lane] : 0.0f;
        obj = (lane < 8) ? so[lane] : 0.0f;
        cls = (lane < 8) ? sc2[lane] : 0.0f;
        #pragma unroll
        for (int o = 4; o > 0; o >>= 1) {
            box += __shfl_down_sync(0xFFFFFFFFu, box, o);
            obj += __shfl_down_sync(0xFFFFFFFFu, obj, o);
            cls += __shfl_down_sync(0xFFFFFFFFu, cls, o);
        }
        if (lane == 0) {
            atomicAdd(out + 0, box + obj + cls);
            atomicAdd(out + 1, box);
            atomicAdd(out + 2, obj);
            atomicAdd(out + 3, cls);
        }
    }
}

extern "C" void kernel_launch(void* const* d_in, const int* in_sizes, int n_in,
                              void* d_out, int out_size) {
    const float* pl  = (const float*)d_in[0];
    const float* pm  = (const float*)d_in[1];
    const float* ps  = (const float*)d_in[2];
    const float* tgt = (const float*)d_in[3];
    float* out = (float*)d_out;

    int B = in_sizes[0] / (3 * 13 * 13 * CH);
    int N = in_sizes[3] / 6;
    int r0 = B * 3 * 13 * 13;
    int r1 = B * 3 * 26 * 26;
    int r2 = B * 3 * 52 * 52;
    int off1 = r0, off2 = r0 + r1;
    int nT = 3 * N;

    int m0 = r0 / 2, m1 = r1 / 2, m2 = r2 / 2;   // row-pair counts (rows even)
    int blk0 = (m0 + MCHUNK - 1) / MCHUNK;
    int blk1 = (m1 + MCHUNK - 1) / MCHUNK;
    int blk2 = (m2 + MCHUNK - 1) / MCHUNK;

    scatter_kernel<<<(nT + 255) / 256, 256>>>(tgt, N, off1, off2, out);
    main_kernel<<<blk0 + blk1 + blk2, TPB>>>(pl, pm, ps, tgt, out,
                                             off1, off2, blk0, blk1,
                                             m0, m1, m2, nT);
}